// round 5
// baseline (speedup 1.0000x reference)
#include <cuda_runtime.h>

// CLUBv2: mi = BETA * sum_d Var_d(y[:, d])
// y: [1024, 256] fp32 row-major. Output: 1 fp32 scalar.
//
//   mi = ( (sum_all y^2)/N - sum_d mu_d^2 ) * BETA
//
// Per-column sums via 2^26 fixed-point int64 relaxed REDs (exactly
// associative -> deterministic). Q as one grand-total scalar. Block-level
// acq_rel ticket (32 arrivals). float4 loads (8 LDG.128/thread).
// Winner: single warp reads 2KB of partials and finishes.

#define N_ROWS 1024
#define N_COLS 256
#define GRID   32
#define ROWS_PER_BLOCK (N_ROWS / GRID)   // 32
#define BETA_F 0.001f
#define FIX_SCALE 67108864.0f            // 2^26
#define FIX_INV   (1.0f / 67108864.0f)

__device__ long long    g_S[N_COLS];   // fixed-point column sums
__device__ long long    g_Qtot;        // fixed-point grand sum of squares
__device__ unsigned int g_ticket = 0;
// Scratch starts zeroed; winner re-zeros after consuming -> every graph
// replay sees zeros. Deterministic.

__device__ __forceinline__ unsigned int atom_add_acq_rel(unsigned int* addr,
                                                         unsigned int v) {
    unsigned int old;
    asm volatile("atom.acq_rel.gpu.global.add.u32 %0, [%1], %2;"
                 : "=r"(old) : "l"(addr), "r"(v) : "memory");
    return old;
}

__global__ void __launch_bounds__(N_COLS, 1)
club_var_kernel(const float* __restrict__ y, float* __restrict__ out) {
    const int t    = threadIdx.x;
    const int b    = blockIdx.x;
    const int lane = t & 31;

    // Phase 1: thread owns column quad (4*quad .. 4*quad+3), covers 8 rows
    // (rp, rp+4, ..., rp+28) of this block's 32-row slice. 8 x LDG.128,
    // fully coalesced (warp = 512B contiguous).
    const int quad = t & 63;        // 0..63
    const int rp   = t >> 6;        // 0..3
    const float4* py = (const float4*)y;
    const float4* p  = py + ((size_t)(b * ROWS_PER_BLOCK + rp) * (N_COLS / 4)) + quad;

    float4 s4 = make_float4(0.f, 0.f, 0.f, 0.f);
    float  q  = 0.0f;
    #pragma unroll
    for (int i = 0; i < ROWS_PER_BLOCK / 4; ++i) {       // 8 iterations
        float4 v = p[i * N_COLS];                        // +4 rows each step
        s4.x += v.x; s4.y += v.y; s4.z += v.z; s4.w += v.w;
        q = fmaf(v.x, v.x, q);
        q = fmaf(v.y, v.y, q);
        q = fmaf(v.z, v.z, q);
        q = fmaf(v.w, v.w, q);
    }

    // Per-column S: 4 relaxed int64 REDs per thread (fire-and-forget,
    // ordered by the ticket's release — not waited on here).
    atomicAdd((unsigned long long*)&g_S[4 * quad + 0],
              (unsigned long long)(long long)llrintf(s4.x * FIX_SCALE));
    atomicAdd((unsigned long long*)&g_S[4 * quad + 1],
              (unsigned long long)(long long)llrintf(s4.y * FIX_SCALE));
    atomicAdd((unsigned long long*)&g_S[4 * quad + 2],
              (unsigned long long)(long long)llrintf(s4.z * FIX_SCALE));
    atomicAdd((unsigned long long*)&g_S[4 * quad + 3],
              (unsigned long long)(long long)llrintf(s4.w * FIX_SCALE));

    // Q: warp shuffle-reduce (fixed order -> deterministic), 1 RED/warp.
    #pragma unroll
    for (int off = 16; off > 0; off >>= 1)
        q += __shfl_down_sync(0xFFFFFFFFu, q, off);
    if (lane == 0)
        atomicAdd((unsigned long long*)&g_Qtot,
                  (unsigned long long)(long long)llrintf(q * FIX_SCALE));

    // Block-level ticket: 32 arrivals total. bar.sync orders all block REDs
    // before t0's gpu-scope release; winner's acquire sees everything.
    __shared__ bool is_last;
    __syncthreads();
    if (t == 0)
        is_last = (atom_add_acq_rel(&g_ticket, 1u) == (unsigned)(GRID - 1));
    __syncthreads();

    if (is_last && t < 32) {
        // Tail: one warp loads 256 int64 partials (2KB), coalesced.
        const longlong2* ps = (const longlong2*)g_S;
        longlong2 v0 = __ldcg(&ps[4 * lane + 0]);
        longlong2 v1 = __ldcg(&ps[4 * lane + 1]);
        longlong2 v2 = __ldcg(&ps[4 * lane + 2]);
        longlong2 v3 = __ldcg(&ps[4 * lane + 3]);
        long long Qf = (lane == 0) ? __ldcg(&g_Qtot) : 0;

        // Reset scratch for next graph replay.
        longlong2 z; z.x = 0; z.y = 0;
        ((longlong2*)g_S)[4 * lane + 0] = z;
        ((longlong2*)g_S)[4 * lane + 1] = z;
        ((longlong2*)g_S)[4 * lane + 2] = z;
        ((longlong2*)g_S)[4 * lane + 3] = z;

        const float invN = 1.0f / (float)N_ROWS;
        const float k = FIX_INV * invN;         // fixed -> mu in one mul
        float m, acc = 0.0f;
        m = (float)v0.x * k; acc = fmaf(m, m, acc);
        m = (float)v0.y * k; acc = fmaf(m, m, acc);
        m = (float)v1.x * k; acc = fmaf(m, m, acc);
        m = (float)v1.y * k; acc = fmaf(m, m, acc);
        m = (float)v2.x * k; acc = fmaf(m, m, acc);
        m = (float)v2.y * k; acc = fmaf(m, m, acc);
        m = (float)v3.x * k; acc = fmaf(m, m, acc);
        m = (float)v3.y * k; acc = fmaf(m, m, acc);

        #pragma unroll
        for (int off = 16; off > 0; off >>= 1)
            acc += __shfl_down_sync(0xFFFFFFFFu, acc, off);

        if (lane == 0) {
            float EQ = (float)Qf * FIX_INV * invN;   // sum_d E[y^2]_d
            out[0] = (EQ - acc) * BETA_F;
            g_Qtot   = 0;
            g_ticket = 0;
        }
    }
}

extern "C" void kernel_launch(void* const* d_in, const int* in_sizes, int n_in,
                              void* d_out, int out_size) {
    (void)in_sizes; (void)n_in; (void)out_size;
    const float* y = (const float*)d_in[0];
    float* out = (float*)d_out;
    club_var_kernel<<<GRID, N_COLS>>>(y, out);
}

// round 6
// speedup vs baseline: 1.4337x; 1.4337x over previous
#include <cuda_runtime.h>

// CLUBv2: mi = BETA * sum_d Var_d(y[:, d])
// y: [1024, 256] fp32 row-major. Output: 1 fp32 scalar.
//
//   mi = ( (sum_all y^2)/N - sum_d mu_d^2 ) * BETA
//
// float4 loads (8x LDG.128/thread) -> smem combine so each column gets
// EXACTLY ONE fixed-point int64 RED per block (32 per address total;
// R5 showed 128/addr quadruples runtime). Q collapsed to 1 RED/block.
// Block-level acq_rel ticket; winner warp reads 2KB and finishes.

#define N_ROWS 1024
#define N_COLS 256
#define GRID   32
#define ROWS_PER_BLOCK (N_ROWS / GRID)   // 32
#define BETA_F 0.001f
#define FIX_SCALE 67108864.0f            // 2^26
#define FIX_INV   (1.0f / 67108864.0f)

__device__ long long    g_S[N_COLS];   // fixed-point column sums
__device__ long long    g_Qtot;        // fixed-point grand sum of squares
__device__ unsigned int g_ticket = 0;
// Scratch starts zeroed; winner re-zeros after consuming -> every graph
// replay sees zeros. Deterministic.

__device__ __forceinline__ unsigned int atom_add_acq_rel(unsigned int* addr,
                                                         unsigned int v) {
    unsigned int old;
    asm volatile("atom.acq_rel.gpu.global.add.u32 %0, [%1], %2;"
                 : "=r"(old) : "l"(addr), "r"(v) : "memory");
    return old;
}

__global__ void __launch_bounds__(N_COLS, 1)
club_var_kernel(const float* __restrict__ y, float* __restrict__ out) {
    const int t    = threadIdx.x;
    const int b    = blockIdx.x;
    const int lane = t & 31;
    const int warp = t >> 5;

    __shared__ float4 sm_s[N_COLS];   // [rp*64 + quad]
    __shared__ float  sm_q[8];

    // Phase 1: thread (quad, rp) covers rows rp, rp+4, ..., rp+28 of this
    // block's 32-row slice for columns 4*quad..4*quad+3. 8x LDG.128,
    // fully coalesced.
    const int quad = t & 63;        // 0..63
    const int rp   = t >> 6;        // 0..3
    const float4* p = (const float4*)y
                    + ((size_t)(b * ROWS_PER_BLOCK + rp) * (N_COLS / 4)) + quad;

    float4 s4 = make_float4(0.f, 0.f, 0.f, 0.f);
    float  q  = 0.0f;
    #pragma unroll
    for (int i = 0; i < ROWS_PER_BLOCK / 4; ++i) {   // 8 iterations
        float4 v = p[i * N_COLS];                    // +4 rows each step
        s4.x += v.x; s4.y += v.y; s4.z += v.z; s4.w += v.w;
        q = fmaf(v.x, v.x, q);
        q = fmaf(v.y, v.y, q);
        q = fmaf(v.z, v.z, q);
        q = fmaf(v.w, v.w, q);
    }

    // Q: warp shuffle-reduce (fixed order -> deterministic).
    #pragma unroll
    for (int off = 16; off > 0; off >>= 1)
        q += __shfl_down_sync(0xFFFFFFFFu, q, off);
    if (lane == 0) sm_q[warp] = q;

    // Stage S partials; combine across the 4 row-phases in smem so each
    // column fires exactly ONE RED per block (contention 32/addr).
    sm_s[t] = s4;
    __syncthreads();

    if (rp == 0) {   // 64 threads: one per column quad
        float4 a = sm_s[quad];
        float4 c = sm_s[64  + quad];
        float4 d = sm_s[128 + quad];
        float4 e = sm_s[192 + quad];
        // Fixed combine order -> deterministic.
        float sx = ((a.x + c.x) + (d.x + e.x));
        float sy = ((a.y + c.y) + (d.y + e.y));
        float sz = ((a.z + c.z) + (d.z + e.z));
        float sw = ((a.w + c.w) + (d.w + e.w));
        atomicAdd((unsigned long long*)&g_S[4 * quad + 0],
                  (unsigned long long)(long long)llrintf(sx * FIX_SCALE));
        atomicAdd((unsigned long long*)&g_S[4 * quad + 1],
                  (unsigned long long)(long long)llrintf(sy * FIX_SCALE));
        atomicAdd((unsigned long long*)&g_S[4 * quad + 2],
                  (unsigned long long)(long long)llrintf(sz * FIX_SCALE));
        atomicAdd((unsigned long long*)&g_S[4 * quad + 3],
                  (unsigned long long)(long long)llrintf(sw * FIX_SCALE));
        if (t == 0) {
            float qb = ((sm_q[0] + sm_q[1]) + (sm_q[2] + sm_q[3]))
                     + ((sm_q[4] + sm_q[5]) + (sm_q[6] + sm_q[7]));
            atomicAdd((unsigned long long*)&g_Qtot,
                      (unsigned long long)(long long)llrintf(qb * FIX_SCALE));
        }
    }

    // Block-level ticket: 32 arrivals. bar.sync gives intra-block hb from
    // all REDs to t0; t0's gpu-scope acq_rel release publishes them.
    __shared__ bool is_last;
    __syncthreads();
    if (t == 0)
        is_last = (atom_add_acq_rel(&g_ticket, 1u) == (unsigned)(GRID - 1));
    __syncthreads();

    if (is_last && t < 32) {
        // Tail: one warp loads 256 int64 partials (2KB), coalesced.
        const longlong2* ps = (const longlong2*)g_S;
        longlong2 v0 = __ldcg(&ps[4 * lane + 0]);
        longlong2 v1 = __ldcg(&ps[4 * lane + 1]);
        longlong2 v2 = __ldcg(&ps[4 * lane + 2]);
        longlong2 v3 = __ldcg(&ps[4 * lane + 3]);
        long long Qf = (lane == 0) ? __ldcg(&g_Qtot) : 0;

        // Reset scratch for next graph replay.
        longlong2 z; z.x = 0; z.y = 0;
        ((longlong2*)g_S)[4 * lane + 0] = z;
        ((longlong2*)g_S)[4 * lane + 1] = z;
        ((longlong2*)g_S)[4 * lane + 2] = z;
        ((longlong2*)g_S)[4 * lane + 3] = z;

        const float invN = 1.0f / (float)N_ROWS;
        const float k = FIX_INV * invN;         // fixed -> mu in one mul
        float m, acc = 0.0f;
        m = (float)v0.x * k; acc = fmaf(m, m, acc);
        m = (float)v0.y * k; acc = fmaf(m, m, acc);
        m = (float)v1.x * k; acc = fmaf(m, m, acc);
        m = (float)v1.y * k; acc = fmaf(m, m, acc);
        m = (float)v2.x * k; acc = fmaf(m, m, acc);
        m = (float)v2.y * k; acc = fmaf(m, m, acc);
        m = (float)v3.x * k; acc = fmaf(m, m, acc);
        m = (float)v3.y * k; acc = fmaf(m, m, acc);

        #pragma unroll
        for (int off = 16; off > 0; off >>= 1)
            acc += __shfl_down_sync(0xFFFFFFFFu, acc, off);

        if (lane == 0) {
            float EQ = (float)Qf * FIX_INV * invN;   // sum_d E[y^2]_d
            out[0] = (EQ - acc) * BETA_F;
            g_Qtot   = 0;
            g_ticket = 0;
        }
    }
}

extern "C" void kernel_launch(void* const* d_in, const int* in_sizes, int n_in,
                              void* d_out, int out_size) {
    (void)in_sizes; (void)n_in; (void)out_size;
    const float* y = (const float*)d_in[0];
    float* out = (float*)d_out;
    club_var_kernel<<<GRID, N_COLS>>>(y, out);
}

// round 7
// speedup vs baseline: 1.9324x; 1.3478x over previous
#include <cuda_runtime.h>

// CLUBv2: mi = BETA * sum_d Var_d(y[:, d])
// y: [1024, 256] fp32 row-major. Output: 1 fp32 scalar.
//
//   mi = ( (sum_all y^2)/N - sum_d mu_d^2 ) * BETA
//
// NO data atomics (R5/R6 showed L2 atomic-ALU drain dominates): each block
// plain-stores its 256 column partials + 1 Q partial to disjoint slots,
// then one acq_rel ticket per block. Winner block reads 32KB coalesced
// from L2 and reduces in a fixed order -> bit-deterministic fp32.

#define N_ROWS 1024
#define N_COLS 256
#define GRID   32
#define ROWS_PER_BLOCK (N_ROWS / GRID)   // 32
#define BETA_F 0.001f

__device__ float        g_ps[GRID * N_COLS];  // per-block column sums (32KB)
__device__ float        g_qp[GRID];           // per-block sum-of-squares
__device__ unsigned int g_ticket = 0;
// g_ps/g_qp are fully overwritten every launch (no reset needed); winner
// resets g_ticket -> every graph replay is identical. Deterministic.

__device__ __forceinline__ unsigned int atom_add_acq_rel(unsigned int* addr,
                                                         unsigned int v) {
    unsigned int old;
    asm volatile("atom.acq_rel.gpu.global.add.u32 %0, [%1], %2;"
                 : "=r"(old) : "l"(addr), "r"(v) : "memory");
    return old;
}

__global__ void __launch_bounds__(N_COLS, 1)
club_var_kernel(const float* __restrict__ y, float* __restrict__ out) {
    const int t    = threadIdx.x;   // column index 0..255
    const int b    = blockIdx.x;
    const int lane = t & 31;
    const int warp = t >> 5;

    // Phase 1: 32 rows per block per column, coalesced scalar loads,
    // fully unrolled -> deep MLP, one DRAM latency exposure.
    float s = 0.0f, q = 0.0f;
    const float* p = y + (size_t)b * ROWS_PER_BLOCK * N_COLS + t;
    #pragma unroll
    for (int r = 0; r < ROWS_PER_BLOCK; ++r) {
        float v = p[r * N_COLS];
        s += v;
        q = fmaf(v, v, q);
    }

    // Per-block column partial: ONE plain store, disjoint slot. No atomics.
    __stcg(&g_ps[b * N_COLS + t], s);

    // Q: warp shuffle-reduce (fixed order), 8 partials through smem.
    #pragma unroll
    for (int off = 16; off > 0; off >>= 1)
        q += __shfl_down_sync(0xFFFFFFFFu, q, off);
    __shared__ float sm_q[8];
    __shared__ bool  is_last;
    if (lane == 0) sm_q[warp] = q;

    // Ticket: bar.sync orders all stores intra-block; t0 stores the block's
    // Q partial, then its gpu-scope acq_rel release publishes everything.
    __syncthreads();
    if (t == 0) {
        float qb = ((sm_q[0] + sm_q[1]) + (sm_q[2] + sm_q[3]))
                 + ((sm_q[4] + sm_q[5]) + (sm_q[6] + sm_q[7]));
        __stcg(&g_qp[b], qb);
        is_last = (atom_add_acq_rel(&g_ticket, 1u) == (unsigned)(GRID - 1));
    }
    __syncthreads();

    if (is_last) {
        // Tail: 32KB from L2, coalesced (warp instr = 1 x 128B line).
        // Thread t accumulates column t across all 32 blocks, fixed order.
        float S = 0.0f;
        #pragma unroll
        for (int bb = 0; bb < GRID; ++bb)
            S += __ldcg(&g_ps[bb * N_COLS + t]);

        // Warp 0 additionally picks up the 32 Q partials (independent path).
        float qv = 0.0f;
        if (warp == 0) qv = __ldcg(&g_qp[lane]);

        const float mu = S * (1.0f / (float)N_ROWS);
        float acc = mu * mu;                 // this thread's mu_d^2

        // Fixed-order reduction of sum_d mu_d^2.
        #pragma unroll
        for (int off = 16; off > 0; off >>= 1)
            acc += __shfl_down_sync(0xFFFFFFFFu, acc, off);
        __shared__ float wsum[8];
        if (lane == 0) wsum[warp] = acc;
        __syncthreads();

        if (warp == 0) {
            // Qtot: fixed-order shuffle tree over the 32 partials.
            #pragma unroll
            for (int off = 16; off > 0; off >>= 1)
                qv += __shfl_down_sync(0xFFFFFFFFu, qv, off);

            float v = (lane < 8) ? wsum[lane] : 0.0f;
            #pragma unroll
            for (int off = 4; off > 0; off >>= 1)
                v += __shfl_down_sync(0xFFFFFFFFu, v, off);

            if (lane == 0) {
                const float EQ = qv * (1.0f / (float)N_ROWS); // sum_d E[y^2]_d
                out[0] = (EQ - v) * BETA_F;
                g_ticket = 0;   // reset for next graph replay
            }
        }
    }
}

extern "C" void kernel_launch(void* const* d_in, const int* in_sizes, int n_in,
                              void* d_out, int out_size) {
    (void)in_sizes; (void)n_in; (void)out_size;
    const float* y = (const float*)d_in[0];
    float* out = (float*)d_out;
    club_var_kernel<<<GRID, N_COLS>>>(y, out);
}